// round 14
// baseline (speedup 1.0000x reference)
#include <cuda_runtime.h>
#include <math.h>
#include <stdint.h>

#define THREADS 256
#define BB 32
#define CC 32
#define HH 128
#define WW2 128
#define HWSZ (HH*WW2)
#define CHWSZ (CC*HWSZ)
#define NTOT (BB*CHWSZ)
#define NB_MAX 2048
#define RTOLF 1e-3f
#define ATOLF 1e-3f

// smem: transformed weights [ci][3][4][co32] f32 (49152B) + halo 32x10x20 f32 (25600B) + red
#define SW_BYTES   (CC*3*4*CC*4)
#define SIN_BYTES  (CC*10*20*4)
#define DSM_BYTES  (SW_BYTES + SIN_BYTES + 128)

#define FB21 ((float)(1.0/5.0))
#define FB31 ((float)(3.0/40.0))
#define FB32 ((float)(9.0/40.0))
#define FB41 ((float)(44.0/45.0))
#define FB42 ((float)(-56.0/15.0))
#define FB43 ((float)(32.0/9.0))
#define FB51 ((float)(19372.0/6561.0))
#define FB52 ((float)(-25360.0/2187.0))
#define FB53 ((float)(64448.0/6561.0))
#define FB54 ((float)(-212.0/729.0))
#define FB61 ((float)(9017.0/3168.0))
#define FB62 ((float)(-355.0/33.0))
#define FB63 ((float)(46732.0/5247.0))
#define FB64 ((float)(49.0/176.0))
#define FB65 ((float)(-5103.0/18656.0))
#define FCS1 ((float)(35.0/384.0))
#define FCS3 ((float)(500.0/1113.0))
#define FCS4 ((float)(125.0/192.0))
#define FCS5 ((float)(-2187.0/6784.0))
#define FCS6 ((float)(11.0/84.0))
#define FCE1 ((float)(35.0/384.0 - 1951.0/21600.0))
#define FCE3 ((float)(500.0/1113.0 - 22642.0/50085.0))
#define FCE4 ((float)(125.0/192.0 - 451.0/720.0))
#define FCE5 ((float)(-2187.0/6784.0 + 12231.0/42400.0))
#define FCE6 ((float)(11.0/84.0 - 649.0/6300.0))
#define FCE7 ((float)(-1.0/60.0))
#define FCM1 ((float)(6025192743.0/30085553152.0/2.0))
#define FCM3 ((float)(51252292925.0/65400821598.0/2.0))
#define FCM4 ((float)(-2691868925.0/45128329728.0/2.0))
#define FCM5 ((float)(187940372067.0/1594534317056.0/2.0))
#define FCM6 ((float)(-1776094331.0/19743644256.0/2.0))
#define FCM7 ((float)(11237099.0/235043384.0/2.0))

__device__ float  g_mem[(size_t)10 * NTOT];
__device__ double g_pA[NB_MAX];
__device__ double g_pB[NB_MAX];
__device__ float  g_feats[BB*CC];
__device__ unsigned          g_cnt = 0;
__device__ volatile unsigned g_gen = 0;

__device__ __forceinline__ float* SLOT(int s){ return g_mem + (size_t)s * NTOT; }

__device__ __forceinline__ void gbar(int nb){
  __syncthreads();
  if (threadIdx.x == 0){
    unsigned gen = g_gen;
    __threadfence();
    if (atomicAdd(&g_cnt, 1u) == (unsigned)(nb - 1)){
      g_cnt = 0u; __threadfence(); g_gen = gen + 1u;
    } else {
      while (g_gen == gen) { __nanosleep(64); }
      __threadfence();
    }
  }
  __syncthreads();
}

__device__ __forceinline__ void red_write(double v, double* s_red, double* part){
  const int lane = threadIdx.x & 31, w = threadIdx.x >> 5;
  #pragma unroll
  for (int o = 16; o; o >>= 1) v += __shfl_down_sync(0xffffffffu, v, o);
  if (lane == 0) s_red[w] = v;
  __syncthreads();
  if (threadIdx.x == 0){
    double s = 0.0;
    #pragma unroll
    for (int i = 0; i < THREADS/32; i++) s += s_red[i];
    part[blockIdx.x] = s;
  }
  __syncthreads();
}

__device__ __forceinline__ double sum_parts(const double* part, int nb, double* s_bc){
  __syncthreads();
  if (threadIdx.x == 0){
    double s = 0.0;
    for (int i = 0; i < nb; i++) s += part[i];
    *s_bc = s;
  }
  __syncthreads();
  double r = *s_bc;
  __syncthreads();
  return r;
}

// dst = tanh(conv3x3_same(src)) via 1D Winograd F(2,3) along w.
// Thread: 2 px (one output pair) x 8 co. Tile: 8 rows x 16 cols.
// MODE 0: plain. MODE 1: fused stage-combine -> dst2. MODE 2: fused error sum.
template<int MODE, int NC>
__device__ void conv_tanh(const float* __restrict__ src, float* __restrict__ dst,
                          float* __restrict__ dst2, const float* const* eA,
                          const float* cf, float dtv,
                          int nb, const float* __restrict__ s_w,
                          float* __restrict__ s_inp, double* s_red)
{
  const int tid = threadIdx.x;
  const int g   = tid & 3;          // co group: co0 = g*8
  const int pp  = tid >> 2;         // 0..63
  const int hh  = pp >> 3;          // 0..7
  const int wp  = (pp & 7) << 1;    // 0,2,...,14
  const int co0 = g << 3;
  const ulonglong2* sw2 = (const ulonglong2*)s_w;
  const int ntiles = BB * 128;      // 16 h-tiles x 8 w-tiles
  double errA = 0.0;
  unsigned long long NEG1;
  { const unsigned un = __float_as_uint(-1.0f);
    asm("mov.b64 %0, {%1, %1};" : "=l"(NEG1) : "r"(un)); }
  for (int tile = blockIdx.x; tile < ntiles; tile += nb){
    const int b = tile >> 7, th = (tile >> 3) & 15, tw = tile & 7;
    const int h0 = th*8, w0 = tw*16;
    const size_t boff = (size_t)b * CHWSZ;
    // halo: 32ci x 10 x 18 (stride 20)
    for (int i = tid; i < CC*180; i += THREADS){
      const int ci = i / 180, rem = i - ci*180;
      const int r = rem / 18, c = rem - r*18;
      const int hy = h0 + r - 1, wx = w0 + c - 1;
      float v = 0.f;
      if (hy >= 0 && hy < HH && wx >= 0 && wx < WW2)
        v = src[boff + (size_t)ci*HWSZ + hy*WW2 + wx];
      s_inp[ci*200 + r*20 + c] = v;
    }
    __syncthreads();

    unsigned long long acc[4][4];   // [i][copair]
    #pragma unroll
    for (int i = 0; i < 4; i++)
      #pragma unroll
      for (int j = 0; j < 4; j++) acc[i][j] = 0ULL;

    #pragma unroll 1
    for (int ci = 0; ci < CC; ci++){
      const float* rowp = s_inp + ci*200 + hh*20 + wp;
      #pragma unroll
      for (int dr = 0; dr < 3; dr++){
        const float2 dA = *(const float2*)(rowp + dr*20);
        const float2 dB = *(const float2*)(rowp + dr*20 + 2);
        const float t0 = dA.x - dB.x;
        const float t1 = dA.y + dB.x;
        const float t2 = dB.x - dA.y;
        const float t3 = dA.y - dB.y;
        unsigned long long T[4];
        { const unsigned u0=__float_as_uint(t0), u1=__float_as_uint(t1);
          const unsigned u2=__float_as_uint(t2), u3=__float_as_uint(t3);
          asm("mov.b64 %0, {%1, %1};" : "=l"(T[0]) : "r"(u0));
          asm("mov.b64 %0, {%1, %1};" : "=l"(T[1]) : "r"(u1));
          asm("mov.b64 %0, {%1, %1};" : "=l"(T[2]) : "r"(u2));
          asm("mov.b64 %0, {%1, %1};" : "=l"(T[3]) : "r"(u3)); }
        const int base = ((ci*3 + dr)*4)*8 + (g << 1);   // ulonglong2 units
        #pragma unroll
        for (int i = 0; i < 4; i++){
          const ulonglong2 wA = sw2[base + i*8];
          const ulonglong2 wB = sw2[base + i*8 + 1];
          asm("fma.rn.f32x2 %0, %1, %2, %0;" : "+l"(acc[i][0]) : "l"(T[i]), "l"(wA.x));
          asm("fma.rn.f32x2 %0, %1, %2, %0;" : "+l"(acc[i][1]) : "l"(T[i]), "l"(wA.y));
          asm("fma.rn.f32x2 %0, %1, %2, %0;" : "+l"(acc[i][2]) : "l"(T[i]), "l"(wB.x));
          asm("fma.rn.f32x2 %0, %1, %2, %0;" : "+l"(acc[i][3]) : "l"(T[i]), "l"(wB.y));
        }
      }
    }

    // output transform + tanh + stores (+ fused modes)
    const size_t rc = (size_t)(h0+hh)*WW2 + (w0+wp);
    #pragma unroll
    for (int cp = 0; cp < 4; cp++){
      unsigned long long y0p, y1p, tt;
      asm("add.rn.f32x2 %0, %1, %2;" : "=l"(y0p) : "l"(acc[0][cp]), "l"(acc[1][cp]));
      asm("add.rn.f32x2 %0, %0, %1;" : "+l"(y0p) : "l"(acc[2][cp]));
      asm("fma.rn.f32x2 %0, %1, %2, %3;" : "=l"(tt)  : "l"(acc[2][cp]), "l"(NEG1), "l"(acc[1][cp]));
      asm("fma.rn.f32x2 %0, %1, %2, %3;" : "=l"(y1p) : "l"(acc[3][cp]), "l"(NEG1), "l"(tt));
      unsigned y0lo, y0hi, y1lo, y1hi;
      asm("mov.b64 {%0, %1}, %2;" : "=r"(y0lo), "=r"(y0hi) : "l"(y0p));
      asm("mov.b64 {%0, %1}, %2;" : "=r"(y1lo), "=r"(y1hi) : "l"(y1p));
      #pragma unroll
      for (int h = 0; h < 2; h++){
        const int ch = co0 + cp*2 + h;
        float2 kv;
        kv.x = tanhf(__uint_as_float(h ? y0hi : y0lo));
        kv.y = tanhf(__uint_as_float(h ? y1hi : y1lo));
        const size_t po = boff + (size_t)ch*HWSZ + rc;
        *(float2*)(dst + po) = kv;
        if (MODE == 1){
          const float2 y0v = *(const float2*)(eA[0] + po);
          float2 kj[(NC > 1) ? (NC - 1) : 1];
          #pragma unroll
          for (int q = 0; q < NC-1; q++) kj[q] = *(const float2*)(eA[q+1] + po);
          float2 o;
          #pragma unroll
          for (int cmp = 0; cmp < 2; cmp++){
            float s = 0.f;
            #pragma unroll
            for (int q = 0; q < NC-1; q++) s = fmaf(cf[q], (&kj[q].x)[cmp], s);
            s = fmaf(cf[NC-1], (&kv.x)[cmp], s);
            (&o.x)[cmp] = fmaf(dtv, s, (&y0v.x)[cmp]);
          }
          *(float2*)(dst2 + po) = o;
        }
        if (MODE == 2){
          const float2 y0v = *(const float2*)(eA[0] + po);
          const float2 y1v = *(const float2*)(eA[1] + po);
          const float2 k1v = *(const float2*)(eA[2] + po);
          const float2 k3v = *(const float2*)(eA[3] + po);
          const float2 k4v = *(const float2*)(eA[4] + po);
          const float2 k5v = *(const float2*)(eA[5] + po);
          const float2 k6v = *(const float2*)(eA[6] + po);
          #pragma unroll
          for (int cmp = 0; cmp < 2; cmp++){
            float e = FCE1 * (&k1v.x)[cmp];
            e = fmaf(FCE3, (&k3v.x)[cmp], e);
            e = fmaf(FCE4, (&k4v.x)[cmp], e);
            e = fmaf(FCE5, (&k5v.x)[cmp], e);
            e = fmaf(FCE6, (&k6v.x)[cmp], e);
            e = fmaf(FCE7, (&kv.x)[cmp],  e);
            e *= dtv;
            const float tol = ATOLF + RTOLF*fmaxf(fabsf((&y0v.x)[cmp]), fabsf((&y1v.x)[cmp]));
            const float r = e / tol;
            errA += (double)r * (double)r;
          }
        }
      }
    }
    __syncthreads();
  }
  if (MODE == 2) red_write(errA, s_red, g_pA);
  gbar(nb);
}

template<int NK>
__device__ void combine(float* __restrict__ dst, const float* __restrict__ base,
                        float dt, const float* const* ks, const float* cf, int nb)
{
  const int gid = blockIdx.x*THREADS + threadIdx.x, nthr = nb*THREADS;
  const float4* b4 = (const float4*)base;
  float4* d4 = (float4*)dst;
  for (int i = gid; i < NTOT/4; i += nthr){
    float4 y = b4[i];
    float sx=0.f, sy=0.f, sz=0.f, sw=0.f;
    #pragma unroll
    for (int j = 0; j < NK; j++){
      float4 k = ((const float4*)ks[j])[i];
      const float c = cf[j];
      sx = fmaf(c,k.x,sx); sy = fmaf(c,k.y,sy); sz = fmaf(c,k.z,sz); sw = fmaf(c,k.w,sw);
    }
    float4 o;
    o.x = fmaf(dt,sx,y.x); o.y = fmaf(dt,sy,y.y); o.z = fmaf(dt,sz,y.z); o.w = fmaf(dt,sw,y.w);
    d4[i] = o;
  }
  gbar(nb);
}

__global__ void __launch_bounds__(THREADS, 2)
odenet_kernel(const float* __restrict__ x, const float* __restrict__ Wconv,
              const float* __restrict__ Wout, const float* __restrict__ bout,
              float* __restrict__ out, int nb)
{
  extern __shared__ char dsm[];
  float* s_w   = (float*)dsm;
  float* s_inp = (float*)(dsm + SW_BYTES);
  double* s_red = (double*)(dsm + SW_BYTES + SIN_BYTES);
  double* s_bc  = s_red + 8;

  const int gid = blockIdx.x*THREADS + threadIdx.x, nthr = nb*THREADS;
  const int tid = threadIdx.x;

  // transformed weights: s_w[((ci*3 + r)*4 + i)*32 + co]
  for (int i = tid; i < CC*CC*3; i += THREADS){
    const int ci = i / 96, rem = i - ci*96;
    const int r = rem >> 5, co = rem & 31;
    const float* wp = Wconv + (co*CC + ci)*9 + r*3;
    const float w0 = wp[0], w1 = wp[1], w2 = wp[2];
    const int base = ((ci*3 + r)*4)*32 + co;
    s_w[base]      = w0;
    s_w[base + 32] = 0.5f*(w0 + w1 + w2);
    s_w[base + 64] = 0.5f*(w0 - w1 + w2);
    s_w[base + 96] = w2;
  }
  {
    float* Y = SLOT(0);
    for (int i = gid; i < NTOT; i += nthr){
      const int c = (i >> 14) & 31, b = i >> 19;
      float v = 0.f;
      if (c < 3) v = x[(size_t)(b*3 + c)*HWSZ + (i & (HWSZ-1))];
      Y[i] = v;
    }
  }
  gbar(nb);

  int iY0=0, iScA=1, iK1=2, iY1K2=3, iK7=8;
  const int iScB=9;

  conv_tanh<0,0>(SLOT(iY0), SLOT(iK1), 0, 0, 0, 0.f, nb, s_w, s_inp, s_red);   // f0

  {
    const float* Y = SLOT(iY0); const float* F = SLOT(iK1);
    double a=0.0, b=0.0;
    for (int i = gid; i < NTOT; i += nthr){
      const float yi = Y[i], fi = F[i];
      const float sc = ATOLF + RTOLF*fabsf(yi);
      const float r0 = yi/sc, r1 = fi/sc;
      a += (double)r0*r0; b += (double)r1*r1;
    }
    red_write(a, s_red, g_pA); red_write(b, s_red, g_pB);
    gbar(nb);
  }
  const float d0 = sqrtf((float)sum_parts(g_pA, nb, s_bc));
  const float d1 = sqrtf((float)sum_parts(g_pB, nb, s_bc));
  const float h0 = (d0 < 1e-5f || d1 < 1e-5f) ? 1e-6f : 0.01f*d0/d1;
  { const float* ks[1] = { SLOT(iK1) }; const float cf[1] = { 1.f };
    combine<1>(SLOT(iScA), SLOT(iY0), h0, ks, cf, nb); }
  conv_tanh<0,0>(SLOT(iScA), SLOT(iY1K2), 0, 0, 0, 0.f, nb, s_w, s_inp, s_red); // f1
  {
    const float* Y = SLOT(iY0); const float* F0 = SLOT(iK1); const float* F1 = SLOT(iY1K2);
    double a = 0.0;
    for (int i = gid; i < NTOT; i += nthr){
      const float sc = ATOLF + RTOLF*fabsf(Y[i]);
      const float r = (F1[i] - F0[i]) / sc;
      a += (double)r*r;
    }
    red_write(a, s_red, g_pA); gbar(nb);
  }
  const float d2 = sqrtf((float)sum_parts(g_pA, nb, s_bc)) / h0;
  float h1;
  if (d1 <= 1e-15f && d2 <= 1e-15f) h1 = fmaxf(1e-6f, h0*1e-3f);
  else                              h1 = powf(0.01f / fmaxf(d1, d2), 0.2f);
  float dt = fminf(100.f*h0, h1);

  float t = 0.f, last_t = 0.f, dt_used = dt;
  int any = 0, iter = 0;

  while (t < 1.0f && iter < 1000 && dt > 0.f){
    iter++;
    { const float* ks[1] = { SLOT(iK1) }; const float cf[1] = { FB21 };
      combine<1>(SLOT(iScA), SLOT(iY0), dt, ks, cf, nb); }
    { const float* eA[2] = { SLOT(iY0), SLOT(iK1) };
      const float cf[2] = { FB31, FB32 };
      conv_tanh<1,2>(SLOT(iScA), SLOT(iY1K2), SLOT(iScB), eA, cf, dt, nb, s_w, s_inp, s_red); }
    { const float* eA[3] = { SLOT(iY0), SLOT(iK1), SLOT(iY1K2) };
      const float cf[3] = { FB41, FB42, FB43 };
      conv_tanh<1,3>(SLOT(iScB), SLOT(4), SLOT(iScA), eA, cf, dt, nb, s_w, s_inp, s_red); }
    { const float* eA[4] = { SLOT(iY0), SLOT(iK1), SLOT(iY1K2), SLOT(4) };
      const float cf[4] = { FB51, FB52, FB53, FB54 };
      conv_tanh<1,4>(SLOT(iScA), SLOT(5), SLOT(iScB), eA, cf, dt, nb, s_w, s_inp, s_red); }
    { const float* eA[5] = { SLOT(iY0), SLOT(iK1), SLOT(iY1K2), SLOT(4), SLOT(5) };
      const float cf[5] = { FB61, FB62, FB63, FB64, FB65 };
      conv_tanh<1,5>(SLOT(iScB), SLOT(6), SLOT(iScA), eA, cf, dt, nb, s_w, s_inp, s_red); }
    { const float* eA[5] = { SLOT(iY0), SLOT(iK1), SLOT(4), SLOT(5), SLOT(6) };
      const float cf[5] = { FCS1, FCS3, FCS4, FCS5, FCS6 };
      conv_tanh<1,5>(SLOT(iScA), SLOT(7), SLOT(iY1K2), eA, cf, dt, nb, s_w, s_inp, s_red); }
    { const float* eA[7] = { SLOT(iY0), SLOT(iY1K2), SLOT(iK1), SLOT(4), SLOT(5), SLOT(6), SLOT(7) };
      conv_tanh<2,0>(SLOT(iY1K2), SLOT(iK7), 0, eA, 0, dt, nb, s_w, s_inp, s_red); }

    const double sum = sum_parts(g_pA, nb, s_bc);
    const float ratio = sqrtf((float)(sum / (double)NTOT));
    const float dfac = (ratio < 1.f) ? 1.0f : 0.2f;
    const float factor = fminf(10.f, fmaxf(0.9f * powf(ratio, -0.2f), dfac));
    const float new_dt = dt * factor;
    if (ratio <= 1.f){
      any = 1; dt_used = dt; last_t = t; t = t + dt;
      if (t >= 1.0f){ dt = new_dt; break; }
      int tmp = iY0; iY0 = iY1K2; iY1K2 = tmp;
      tmp = iK1; iK1 = iK7; iK7 = tmp;
    }
    dt = new_dt;
  }

  // interpolate to t=1, fused with global spatial max
  {
    const float xr = any ? (1.0f - last_t) / (t - last_t) : 0.f;
    const float dtu = dt_used;
    const float* Y0 = SLOT(iY0); const float* Y1 = SLOT(iY1K2);
    const float* K1 = SLOT(iK1); const float* K3 = SLOT(4);
    const float* K4 = SLOT(5);   const float* K5 = SLOT(6);
    const float* K6 = SLOT(7);   const float* K7 = SLOT(iK7);
    const int gw = gid >> 5, lane = threadIdx.x & 31, nw = nthr >> 5;
    for (int p = gw; p < BB*CC; p += nw){
      const size_t base = (size_t)p * HWSZ;
      float m = -3.402823466e38f;
      for (int i = lane; i < HWSZ; i += 32){
        const size_t idx = base + i;
        const float y0 = Y0[idx];
        float v = y0;
        if (any){
          const float y1 = Y1[idx];
          const float k1 = K1[idx], k7 = K7[idx];
          float s = FCM1*k1;
          s = fmaf(FCM3, K3[idx], s); s = fmaf(FCM4, K4[idx], s);
          s = fmaf(FCM5, K5[idx], s); s = fmaf(FCM6, K6[idx], s);
          s = fmaf(FCM7, k7, s);
          const float ym = fmaf(dtu, s, y0);
          const float dy0 = k1*dtu, dy1 = k7*dtu;
          const float ca = 2.f*(dy1 - dy0) - 8.f*(y1 + y0) + 16.f*ym;
          const float cb = 5.f*dy0 - 3.f*dy1 + 18.f*y0 + 14.f*y1 - 32.f*ym;
          const float cc = -4.f*dy0 + dy1 - 11.f*y0 - 5.f*y1 + 16.f*ym;
          v = fmaf(fmaf(fmaf(fmaf(ca, xr, cb), xr, cc), xr, dy0), xr, y0);
        }
        m = fmaxf(m, v);
      }
      #pragma unroll
      for (int o = 16; o; o >>= 1) m = fmaxf(m, __shfl_down_sync(0xffffffffu, m, o));
      if (lane == 0) g_feats[p] = m;
    }
    gbar(nb);
  }

  for (int idx = gid; idx < BB*1000; idx += nthr){
    const int b = idx / 1000, n = idx - b*1000;
    const float* f = g_feats + b*CC;
    const float* w = Wout + n*CC;
    float s = bout[n];
    #pragma unroll
    for (int c = 0; c < CC; c++) s = fmaf(f[c], __ldg(w + c), s);
    out[idx] = s;
  }
}

extern "C" void kernel_launch(void* const* d_in, const int* in_sizes, int n_in,
                              void* d_out, int out_size)
{
  const float* x     = (const float*)d_in[0];
  const float* Wconv = (const float*)d_in[1];
  const float* Wout  = (const float*)d_in[2];
  const float* bout  = (const float*)d_in[3];
  float* out = (float*)d_out;

  cudaFuncSetAttribute(odenet_kernel, cudaFuncAttributeMaxDynamicSharedMemorySize, DSM_BYTES);

  int dev = 0; cudaGetDevice(&dev);
  int smCount = 0;
  cudaDeviceGetAttribute(&smCount, cudaDevAttrMultiProcessorCount, dev);
  int bpm = 0;
  cudaOccupancyMaxActiveBlocksPerMultiprocessor(&bpm, odenet_kernel, THREADS, DSM_BYTES);
  if (bpm < 1) bpm = 1;
  int nb = smCount * bpm;
  if (nb > NB_MAX) nb = NB_MAX;
  if (nb < 1) nb = 1;

  odenet_kernel<<<nb, THREADS, DSM_BYTES>>>(x, Wconv, Wout, bout, out, nb);
}